// round 11
// baseline (speedup 1.0000x reference)
#include <cuda_runtime.h>
#include <math_constants.h>
#include <cstdint>

#define B_  8
#define N_  1024
#define C_  768
#define H_  12
#define D_  64
#define SCALE_ 0.125f

// Scratch (device globals: no allocation allowed)
__device__ float g_qkv[(size_t)B_ * N_ * 3 * C_];   // [8192][2304]
__device__ float g_attn[(size_t)B_ * N_ * C_];      // [8192][768]
__device__ float g_rsum[(size_t)B_ * H_ * N_];      // softmax row sums

// Feature gate: tcgen05 only exists in the sm_103a/sm_100a-specific cubin.
#if defined(__CUDA_ARCH_FEAT_SM103_ALL) || defined(__CUDA_ARCH_FEAT_SM100_ALL)
#define HAS_TCGEN05 1
#else
#define HAS_TCGEN05 0
#endif

#if HAS_TCGEN05
// ===========================================================================
// PTX helpers (verified encodings only)
// ===========================================================================
__device__ __forceinline__ uint32_t smem_u32(const void* p) {
    uint32_t a;
    asm("{ .reg .u64 t; cvta.to.shared.u64 t, %1; cvt.u32.u64 %0, t; }"
        : "=r"(a) : "l"(p));
    return a;
}
__device__ __forceinline__ uint32_t elect_one() {
    uint32_t pred;
    asm volatile("{\n\t.reg .pred p;\n\telect.sync _|p, 0xFFFFFFFF;\n\t"
                 "selp.b32 %0, 1, 0, p;\n\t}" : "=r"(pred));
    return pred;
}
#define TC_ALLOC(sm_addr, n) \
    asm volatile("tcgen05.alloc.cta_group::1.sync.aligned.shared::cta.b32 [%0], %1;" \
                 :: "r"(sm_addr), "r"((uint32_t)(n)) : "memory")
#define TC_DEALLOC(tm, n) \
    asm volatile("tcgen05.dealloc.cta_group::1.sync.aligned.b32 %0, %1;" \
                 :: "r"(tm), "r"((uint32_t)(n)))
#define TC_RELINQ() \
    asm volatile("tcgen05.relinquish_alloc_permit.cta_group::1.sync.aligned;")
#define TC_COMMIT(mbar) \
    asm volatile("tcgen05.commit.cta_group::1.mbarrier::arrive::one.shared::cluster.b64 [%0];" \
                 :: "r"(mbar) : "memory")
#define TC_FENCE_AFTER()  asm volatile("tcgen05.fence::after_thread_sync;" ::: "memory")
#define TC_FENCE_BEFORE() asm volatile("tcgen05.fence::before_thread_sync;" ::: "memory")
#define TC_WAIT_LD() asm volatile("tcgen05.wait::ld.sync.aligned;" ::: "memory")
#define MBAR_INIT(a, c) \
    asm volatile("mbarrier.init.shared.b64 [%0], %1;" :: "r"(a), "r"((uint32_t)(c)) : "memory")
#define MBAR_WAIT(a, ph) do {                                                   \
    uint32_t _m = (a), _p = (ph), _d;                                           \
    asm volatile("{\n\t.reg .pred p;\n\t"                                       \
        "mbarrier.try_wait.parity.acquire.cta.shared::cta.b64 p, [%1], %2;\n\t" \
        "selp.b32 %0, 1, 0, p;\n\t}" : "=r"(_d) : "r"(_m), "r"(_p) : "memory"); \
    if (!_d) {                                                                   \
        asm volatile("{\n\t.reg .pred P1;\n\t"                                   \
            "W%=:\n\t"                                                           \
            "mbarrier.try_wait.parity.acquire.cta.shared::cta.b64 P1, [%0], %1, 0x989680;\n\t" \
            "@P1 bra.uni D%=;\n\t"                                               \
            "bra.uni W%=;\n\t"                                                   \
            "D%=:\n\t}" :: "r"(_m), "r"(_p) : "memory");                         \
    } } while (0)
#define TC_LD_X32(r, tm) \
    asm volatile("tcgen05.ld.sync.aligned.32x32b.x32.b32 " \
        "{%0, %1, %2, %3, %4, %5, %6, %7, %8, %9, %10, %11, %12, %13, %14, %15, " \
        " %16, %17, %18, %19, %20, %21, %22, %23, %24, %25, %26, %27, %28, %29, %30, %31}, [%32];" \
        : "=r"((r)[0]),  "=r"((r)[1]),  "=r"((r)[2]),  "=r"((r)[3]),  \
          "=r"((r)[4]),  "=r"((r)[5]),  "=r"((r)[6]),  "=r"((r)[7]),  \
          "=r"((r)[8]),  "=r"((r)[9]),  "=r"((r)[10]), "=r"((r)[11]), \
          "=r"((r)[12]), "=r"((r)[13]), "=r"((r)[14]), "=r"((r)[15]), \
          "=r"((r)[16]), "=r"((r)[17]), "=r"((r)[18]), "=r"((r)[19]), \
          "=r"((r)[20]), "=r"((r)[21]), "=r"((r)[22]), "=r"((r)[23]), \
          "=r"((r)[24]), "=r"((r)[25]), "=r"((r)[26]), "=r"((r)[27]), \
          "=r"((r)[28]), "=r"((r)[29]), "=r"((r)[30]), "=r"((r)[31]) \
        : "r"(tm))

static constexpr uint64_t DESC_SW128 =
    (uint64_t(2) << 61) | (uint64_t(1) << 46) | (uint64_t(64) << 32) | (uint64_t(1) << 16);
__device__ __forceinline__ uint64_t mk_desc(uint32_t addr) {
    return DESC_SW128 | ((uint64_t)(addr >> 4) & 0x3FFF);
}
__device__ __forceinline__ uint32_t sw128(uint32_t off) {
    return off ^ ((off >> 3) & 0x70);
}
// cvt2(a,b): lo half = a, hi half = b
__device__ __forceinline__ uint32_t cvt2(float a, float b) {
    uint32_t d;
    asm("cvt.rn.bf16x2.f32 %0, %1, %2;" : "=r"(d) : "f"(b), "f"(a));
    return d;
}
// SS-mode bf16 MMA
__device__ __forceinline__ void mma_f16_ss(uint32_t d, uint64_t ad, uint64_t bd,
                                           uint32_t idesc, uint32_t en) {
    asm volatile(
        "{\n\t.reg .pred p;\n\t"
        "setp.ne.u32 p, %5, 0;\n\t"
        "tcgen05.mma.cta_group::1.kind::f16 [%0], %1, %2, %3, {%4, %4, %4, %4}, p;\n\t}"
        :: "r"(d), "l"(ad), "l"(bd), "r"(idesc), "r"(0u), "r"(en) : "memory");
}

// idesc: dtype=F32(bit4), atype=btype=BF16, N field = N/8 << 17, M = M/16 << 24
static constexpr uint32_t IDESC_128 =
    (1u << 4) | (1u << 7) | (1u << 10) | (16u << 17) | (8u << 24);   // M=128,N=128
static constexpr uint32_t IDESC_N64 =
    (1u << 4) | (1u << 7) | (1u << 10) | (8u << 17) | (8u << 24);    // M=128,N=64

__device__ __forceinline__ void conv8(char* smb, uint32_t HI, uint32_t LO,
                                      const float* src, int r, int g) {
    float4 v0 = *(const float4*)src;
    float4 v1 = *(const float4*)(src + 4);
    uint32_t h0 = cvt2(v0.x, v0.y), h1 = cvt2(v0.z, v0.w);
    uint32_t h2 = cvt2(v1.x, v1.y), h3 = cvt2(v1.z, v1.w);
    float l0 = v0.x - __uint_as_float(h0 << 16);
    float l1 = v0.y - __uint_as_float(h0 & 0xffff0000u);
    float l2 = v0.z - __uint_as_float(h1 << 16);
    float l3 = v0.w - __uint_as_float(h1 & 0xffff0000u);
    float l4 = v1.x - __uint_as_float(h2 << 16);
    float l5 = v1.y - __uint_as_float(h2 & 0xffff0000u);
    float l6 = v1.z - __uint_as_float(h3 << 16);
    float l7 = v1.w - __uint_as_float(h3 & 0xffff0000u);
    uint32_t sw = sw128((uint32_t)(r * 128 + g * 16));
    uint4 hv; hv.x = h0; hv.y = h1; hv.z = h2; hv.w = h3;
    *(uint4*)(smb + HI + sw) = hv;
    uint4 lv;
    lv.x = cvt2(l0, l1); lv.y = cvt2(l2, l3);
    lv.z = cvt2(l4, l5); lv.w = cvt2(l6, l7);
    *(uint4*)(smb + LO + sw) = lv;
}
#endif  // HAS_TCGEN05

// ===========================================================================
// Pipelined GEMM:  C = A @ W^T (+ epilogue). Double-buffered conv/MMA.
// Even chunks commit on MB0, odd on MB1 (keeps parity waits sequential).
// ===========================================================================
template <int MODE>
__global__ __launch_bounds__(256, 1) void mma_gemm(
    const float* __restrict__ A, const float* __restrict__ W,
    float* __restrict__ Cout, int Nn, int K,
    const float* __restrict__ extra)
{
#if HAS_TCGEN05
    extern __shared__ char smc[];
    const uint32_t smem_base = smem_u32(smc);
    const uint32_t TMP = 0, MB0 = 8, MB1 = 16;
    // per-buffer layout: AHI +0, ALO +16K, WHI +32K, WLO +48K; buf stride 64K
    const uint32_t BUF0 = 1024;

    const int tid = threadIdx.x;
    const int wid = tid >> 5;
    const int m0 = blockIdx.y * 128;
    const int n0 = blockIdx.x * 128;

    if (wid == 0) {
        TC_ALLOC(smem_base + TMP, 128);
        TC_RELINQ();
    }
    if (tid == 0) { MBAR_INIT(smem_base + MB0, 1); MBAR_INIT(smem_base + MB1, 1); }
    __syncthreads();
    uint32_t tmem;
    asm volatile("ld.shared.b32 %0, [%1];" : "=r"(tmem) : "r"(smem_base + TMP));

    const int nch = K / 64;   // 12
    for (int ch = 0; ch < nch; ++ch) {
        const uint32_t buf = BUF0 + (uint32_t)(ch & 1) * 65536;
        // buffer reuse: MMA(ch-2) must be done (same-parity barrier, phase (ch-2)/2)
        if (ch >= 2)
            MBAR_WAIT(smem_base + ((ch & 1) ? MB1 : MB0), (uint32_t)(((ch >> 1) - 1) & 1));

        const int kt = ch * 64;
#pragma unroll
        for (int it = 0; it < 4; ++it) {
            int task = tid + it * 256;
            int r = task >> 3;
            int g = task & 7;
            conv8(smc, buf, buf + 16384, A + (size_t)(m0 + r) * K + kt + g * 8, r, g);
            conv8(smc, buf + 32768, buf + 49152, W + (size_t)(n0 + r) * K + kt + g * 8, r, g);
        }
        __syncthreads();

        if (wid == 0) {
            asm volatile("fence.proxy.async.shared::cta;" ::: "memory");
            if (elect_one()) {
                const uint64_t dAhi = mk_desc(smem_base + buf);
                const uint64_t dAlo = mk_desc(smem_base + buf + 16384);
                const uint64_t dWhi = mk_desc(smem_base + buf + 32768);
                const uint64_t dWlo = mk_desc(smem_base + buf + 49152);
#pragma unroll
                for (int ks = 0; ks < 4; ++ks) {
                    uint64_t o = (uint64_t)(ks * 2);
                    mma_f16_ss(tmem, dAhi + o, dWhi + o, IDESC_128,
                               (uint32_t)((ch | ks) != 0));
                    mma_f16_ss(tmem, dAhi + o, dWlo + o, IDESC_128, 1u);
                    mma_f16_ss(tmem, dAlo + o, dWhi + o, IDESC_128, 1u);
                }
                TC_COMMIT(smem_base + ((ch & 1) ? MB1 : MB0));
            }
        }
        // no wait — next conv targets the other buffer
    }
    // drain: last even commit (nch-2) on MB0 phase (nch-2)/2, last odd on MB1
    MBAR_WAIT(smem_base + MB0, (uint32_t)(((nch - 2) >> 1) & 1));
    MBAR_WAIT(smem_base + MB1, (uint32_t)(((nch - 1) >> 1) & 1));
    TC_FENCE_AFTER();

    const int lane = tid & 31;
    const int sub = wid & 3;
    const int cb = (wid >> 2) * 64;
    uint32_t dr[64];
    TC_LD_X32(dr, tmem + cb);
    TC_LD_X32(dr + 32, tmem + cb + 32);
    TC_WAIT_LD();
    TC_FENCE_BEFORE();

    const int row = m0 + sub * 32 + lane;
    float* dst = Cout + (size_t)row * Nn + n0 + cb;
#pragma unroll
    for (int j4 = 0; j4 < 16; ++j4) {
        float4 v;
        float* vv = (float*)&v;
#pragma unroll
        for (int u = 0; u < 4; ++u) {
            int j = j4 * 4 + u;
            float val = __uint_as_float(dr[j]);
            int cc = n0 + cb + j;
            if (MODE == 0) {
                if (cc >= 768 && cc < 1536) val += __ldg(extra + cc - 768);
            } else {
                val += __ldg(extra + cc);
            }
            vv[u] = val;
        }
        *(float4*)(dst + j4 * 4) = v;
    }

    __syncthreads();
    if (wid == 0) {
        TC_DEALLOC(tmem, 128);
    }
#else
    extern __shared__ char smc[];
    float* As = (float*)smc;
    float* Bs = (float*)smc + 16 * 132;

    const int tid = threadIdx.x;
    const int tx = tid & 15;
    const int ty = tid >> 4;
    const int m0 = blockIdx.y * 128;
    const int n0 = blockIdx.x * 128;

    float acc[8][8];
#pragma unroll
    for (int i = 0; i < 8; i++)
#pragma unroll
        for (int j = 0; j < 8; j++) acc[i][j] = 0.f;

    const int rowL = tid >> 2;
    const int c4   = tid & 3;

    for (int kt = 0; kt < K; kt += 16) {
#pragma unroll
        for (int it = 0; it < 2; ++it) {
            int r = rowL + it * 64;
            float4 va = *(const float4*)(A + (size_t)(m0 + r) * K + kt + c4 * 4);
            float4 vb = *(const float4*)(W + (size_t)(n0 + r) * K + kt + c4 * 4);
            int cb2 = c4 * 4;
            As[(cb2 + 0) * 132 + r] = va.x;
            As[(cb2 + 1) * 132 + r] = va.y;
            As[(cb2 + 2) * 132 + r] = va.z;
            As[(cb2 + 3) * 132 + r] = va.w;
            Bs[(cb2 + 0) * 132 + r] = vb.x;
            Bs[(cb2 + 1) * 132 + r] = vb.y;
            Bs[(cb2 + 2) * 132 + r] = vb.z;
            Bs[(cb2 + 3) * 132 + r] = vb.w;
        }
        __syncthreads();

#pragma unroll
        for (int k = 0; k < 16; k++) {
            float a[8], b[8];
            *(float4*)(a)     = *(const float4*)&As[k * 132 + ty * 4];
            *(float4*)(a + 4) = *(const float4*)&As[k * 132 + 64 + ty * 4];
            *(float4*)(b)     = *(const float4*)&Bs[k * 132 + tx * 4];
            *(float4*)(b + 4) = *(const float4*)&Bs[k * 132 + 64 + tx * 4];
#pragma unroll
            for (int i = 0; i < 8; i++)
#pragma unroll
                for (int j = 0; j < 8; j++) acc[i][j] += a[i] * b[j];
        }
        __syncthreads();
    }

#pragma unroll
    for (int i = 0; i < 8; i++) {
        int r = m0 + ((i < 4) ? (ty * 4 + i) : (64 + ty * 4 + (i - 4)));
#pragma unroll
        for (int jh = 0; jh < 2; jh++) {
            int c = n0 + jh * 64 + tx * 4;
            float v[4];
#pragma unroll
            for (int u = 0; u < 4; u++) v[u] = acc[i][(jh < 1 ? 0 : 4) + u];
            if (MODE == 0) {
#pragma unroll
                for (int u = 0; u < 4; u++) {
                    int cc = c + u;
                    if (cc >= 768 && cc < 1536) v[u] += extra[cc - 768];
                }
            } else {
#pragma unroll
                for (int u = 0; u < 4; u++) v[u] += extra[c + u];
            }
            float4 o;
            o.x = v[0]; o.y = v[1]; o.z = v[2]; o.w = v[3];
            *(float4*)(Cout + (size_t)r * Nn + c) = o;
        }
    }
#endif
}

// ===========================================================================
// Pipelined tcgen05 attention. K/V^T double-buffered: conv(t+1) overlaps
// PV(t). Single MBP barrier: epi(t) waits commit t-1 (pending <= req+1,
// alias-safe). Queue order (PV(t-1) before QK(t)) protects S/O hazards.
// ===========================================================================
__global__ __launch_bounds__(256, 1) void attn_mma(float* __restrict__ probs,
                                                   float* __restrict__ rsum)
{
#if HAS_TCGEN05
    extern __shared__ char smc[];
    const uint32_t base = smem_u32(smc);
    const uint32_t TMP = 0, MBQ = 8, MBP = 16, RS = 128;
    const uint32_t QHI = 1024, QLO = QHI + 16384;           // [128 q][64 d]
    const uint32_t KB0 = 33792;                              // K bufs: 2 x 32KB
    const uint32_t VB0 = 99328;                              // VT bufs: 2 x 32KB
    const uint32_t PHI = 164864, PLO = PHI + 32768;          // 2 x [128 q][64 k]

    const int tid = threadIdx.x;
    const int wid = tid >> 5;
    const int lane = tid & 31;
    const int bh = blockIdx.y;
    const int b  = bh / H_;
    const int h  = bh % H_;
    const int q0 = blockIdx.x * 128;

    if (wid == 0) {
        TC_ALLOC(base + TMP, 256);
        TC_RELINQ();
    }
    if (tid == 0) { MBAR_INIT(base + MBQ, 1); MBAR_INIT(base + MBP, 1); }
    __syncthreads();
    uint32_t tmem;
    asm volatile("ld.shared.b32 %0, [%1];" : "=r"(tmem) : "r"(base + TMP));
    const uint32_t S_ = tmem, O_ = tmem + 128;

    const float* qg = g_qkv + (size_t)b * N_ * 2304 + (size_t)q0 * 2304 + h * 64;
    const float* kg = g_qkv + (size_t)b * N_ * 2304 + 768  + h * 64;
    const float* vg = g_qkv + (size_t)b * N_ * 2304 + 1536 + h * 64;

    // convert Q tile (128 rows x 64 d) to bf16 hi/lo
#pragma unroll
    for (int it = 0; it < 4; ++it) {
        int task = tid + it * 256;
        int r = task >> 3, g = task & 7;
        conv8(smc, QHI, QLO, qg + (size_t)r * 2304 + g * 8, r, g);
    }

    const uint64_t dQhi = mk_desc(base + QHI), dQlo = mk_desc(base + QLO);

    const int sub = wid & 3;
    const int row = sub * 32 + lane;              // q row within tile
    const int cb = (wid >> 2) * 64;               // k-col half for S epilogue
    float rs_acc = 0.f;

    for (int t = 0; t < 8; ++t) {
        const uint32_t kb = KB0 + (uint32_t)(t & 1) * 32768;
        const uint32_t vb = VB0 + (uint32_t)(t & 1) * 32768;

        // ---- conv K tile [128 k][64 d] hi/lo into buf ----
        // (buffer reuse safe: epi(t-1) waited PV commit t-2)
        const float* kt = kg + (size_t)t * 128 * 2304;
#pragma unroll
        for (int it = 0; it < 4; ++it) {
            int task = tid + it * 256;
            int r = task >> 3, g = task & 7;
            conv8(smc, kb, kb + 16384, kt + (size_t)r * 2304 + g * 8, r, g);
        }
        // ---- build V^T [64 d][128 k] hi/lo (2 chunks of [64][64]) ----
        {
            const float* vt = vg + (size_t)t * 128 * 2304;
            const int k0 = (tid & 15) * 8;
            const int d0 = (tid >> 4) * 4;
            float4 vr[8];
#pragma unroll
            for (int i = 0; i < 8; ++i)
                vr[i] = *(const float4*)(vt + (size_t)(k0 + i) * 2304 + d0);
            const int chunk = k0 >> 6;
            const int kl = k0 & 63;
#pragma unroll
            for (int d = 0; d < 4; ++d) {
                uint4 hv4, lv4;
                uint32_t* hw = (uint32_t*)&hv4;
                uint32_t* lw = (uint32_t*)&lv4;
#pragma unroll
                for (int j = 0; j < 4; ++j) {
                    float a = ((const float*)&vr[2 * j])[d];
                    float bb = ((const float*)&vr[2 * j + 1])[d];
                    uint32_t hvb = cvt2(a, bb);
                    hw[j] = hvb;
                    float la = a - __uint_as_float(hvb << 16);
                    float lb = bb - __uint_as_float(hvb & 0xffff0000u);
                    lw[j] = cvt2(la, lb);
                }
                uint32_t off = sw128((uint32_t)((d0 + d) * 128 + kl * 2));
                *(uint4*)(smc + vb + chunk * 8192 + off) = hv4;
                *(uint4*)(smc + vb + 16384 + chunk * 8192 + off) = lv4;
            }
        }
        __syncthreads();

        // ---- QK^T -> S (queued after PV(t-1); in-order pipe = no S hazard) ----
        if (wid == 0) {
            asm volatile("fence.proxy.async.shared::cta;" ::: "memory");
            if (elect_one()) {
                const uint64_t dKhi = mk_desc(base + kb);
                const uint64_t dKlo = mk_desc(base + kb + 16384);
#pragma unroll
                for (int ks = 0; ks < 4; ++ks) {
                    uint64_t o = (uint64_t)(ks * 2);
                    mma_f16_ss(S_, dQhi + o, dKhi + o, IDESC_128, (uint32_t)(ks != 0));
                    mma_f16_ss(S_, dQhi + o, dKlo + o, IDESC_128, 1u);
                    mma_f16_ss(S_, dQlo + o, dKhi + o, IDESC_128, 1u);
                }
                TC_COMMIT(base + MBQ);
            }
        }
        MBAR_WAIT(base + MBQ, (uint32_t)(t & 1));
        // P buffer reuse: PV(t-1) must be done before P store below
        if (t >= 1) MBAR_WAIT(base + MBP, (uint32_t)((t - 1) & 1));
        TC_FENCE_AFTER();

        // ---- epilogue: LDTM S -> exp -> probs(gmem), rowsum, P -> smem ----
        float* prow = probs
            ? probs + ((size_t)bh * N_ + q0 + row) * N_ + t * 128 + cb
            : nullptr;
        const int pchunk = cb >> 6;
#pragma unroll
        for (int c = 0; c < 2; ++c) {
            uint32_t sr[32];
            TC_LD_X32(sr, S_ + cb + c * 32);
            TC_WAIT_LD();
            float p[32];
#pragma unroll
            for (int j = 0; j < 32; ++j) {
                p[j] = __expf(__uint_as_float(sr[j]) * SCALE_);
                rs_acc += p[j];
            }
            if (prow) {
#pragma unroll
                for (int j4 = 0; j4 < 8; ++j4) {
                    float4 v;
                    v.x = p[j4 * 4 + 0]; v.y = p[j4 * 4 + 1];
                    v.z = p[j4 * 4 + 2]; v.w = p[j4 * 4 + 3];
                    *(float4*)(prow + c * 32 + j4 * 4) = v;
                }
            }
#pragma unroll
            for (int g = 0; g < 4; ++g) {
                uint4 hv4, lv4;
                uint32_t* hw = (uint32_t*)&hv4;
                uint32_t* lw = (uint32_t*)&lv4;
#pragma unroll
                for (int j = 0; j < 4; ++j) {
                    float a = p[8 * g + 2 * j], bb = p[8 * g + 2 * j + 1];
                    uint32_t hvb = cvt2(a, bb);
                    hw[j] = hvb;
                    float la = a - __uint_as_float(hvb << 16);
                    float lb = bb - __uint_as_float(hvb & 0xffff0000u);
                    lw[j] = cvt2(la, lb);
                }
                uint32_t off = sw128((uint32_t)(row * 128 + c * 64 + g * 16));
                *(uint4*)(smc + PHI + pchunk * 16384 + off) = hv4;
                *(uint4*)(smc + PLO + pchunk * 16384 + off) = lv4;
            }
        }
        __syncthreads();

        // ---- PV: O += P @ (V^T)^T ----
        if (wid == 0) {
            asm volatile("fence.proxy.async.shared::cta;" ::: "memory");
            if (elect_one()) {
#pragma unroll
                for (int c2 = 0; c2 < 2; ++c2) {
                    uint64_t dPh = mk_desc(base + PHI + c2 * 16384);
                    uint64_t dPl = mk_desc(base + PLO + c2 * 16384);
                    uint64_t dVh = mk_desc(base + vb + c2 * 8192);
                    uint64_t dVl = mk_desc(base + vb + 16384 + c2 * 8192);
#pragma unroll
                    for (int ks = 0; ks < 4; ++ks) {
                        uint64_t o = (uint64_t)(ks * 2);
                        mma_f16_ss(O_, dPh + o, dVh + o, IDESC_N64,
                                   (uint32_t)((t | c2 | ks) != 0));
                        mma_f16_ss(O_, dPh + o, dVl + o, IDESC_N64, 1u);
                        mma_f16_ss(O_, dPl + o, dVh + o, IDESC_N64, 1u);
                    }
                }
                TC_COMMIT(base + MBP);
            }
        }
        // no wait — conv(t+1) targets the other buffer
    }

    MBAR_WAIT(base + MBP, 1u);   // PV of t=7 (commit 7, parity 1)
    TC_FENCE_AFTER();

    // rowsum reduce across the two k-halves
    float* RSm = (float*)(smc + RS);
    if (wid < 4) RSm[row] = rs_acc;
    __syncthreads();
    if (wid >= 4) RSm[row] += rs_acc;
    __syncthreads();

    if (wid < 4) {
        float rsv = RSm[row];
        rsum[(size_t)bh * N_ + q0 + row] = rsv;
        float inv = 1.f / rsv;
        uint32_t orr[64];
        TC_LD_X32(orr, O_);
        TC_LD_X32(orr + 32, O_ + 32);
        TC_WAIT_LD();
        TC_FENCE_BEFORE();
        float* dst = g_attn + ((size_t)b * N_ + q0 + row) * C_ + h * 64;
#pragma unroll
        for (int j4 = 0; j4 < 16; ++j4) {
            float4 v;
            v.x = __uint_as_float(orr[j4 * 4 + 0]) * inv;
            v.y = __uint_as_float(orr[j4 * 4 + 1]) * inv;
            v.z = __uint_as_float(orr[j4 * 4 + 2]) * inv;
            v.w = __uint_as_float(orr[j4 * 4 + 3]) * inv;
            *(float4*)(dst + j4 * 4) = v;
        }
    }
    __syncthreads();
    if (wid == 0) TC_DEALLOC(tmem, 256);
#endif  // HAS_TCGEN05 (base-arch cubin never runs on GB300)
}

__global__ __launch_bounds__(256) void norm_kernel(float* __restrict__ probs,
                                                   const float* __restrict__ rsum)
{
    size_t row = blockIdx.x;
    float inv = 1.f / rsum[row];
    float4* p = (float4*)(probs + row * N_);
    float4 v = p[threadIdx.x];
    v.x *= inv; v.y *= inv; v.z *= inv; v.w *= inv;
    p[threadIdx.x] = v;
}

// ===========================================================================
extern "C" void kernel_launch(void* const* d_in, const int* in_sizes, int n_in,
                              void* d_out, int out_size)
{
    const float* x     = (const float*)d_in[0];
    const float* se    = (const float*)d_in[1];
    const float* wqkv  = (const float*)d_in[2];
    const float* wproj = (const float*)d_in[3];
    const float* bproj = (const float*)d_in[4];

    float* out = (float*)d_out;
    const long long OUTN = (long long)B_ * N_ * C_;
    const long long PRN  = (long long)B_ * H_ * N_ * N_;

    float* probs = nullptr;
    bool do_proj = true;
    if ((long long)out_size >= OUTN + PRN) {
        probs = out + OUTN;
    } else if ((long long)out_size == PRN) {
        probs = out;
        do_proj = false;
    }

    float* qkv = nullptr;
    float* attn = nullptr;
    float* rsum = nullptr;
    cudaGetSymbolAddress((void**)&qkv, g_qkv);
    cudaGetSymbolAddress((void**)&attn, g_attn);
    cudaGetSymbolAddress((void**)&rsum, g_rsum);

    const int GEMM_SMEM = 1024 + 8 * 16384;                  // 132096
    const int ATTN_SMEM = 1024 + 2 * 16384 + 4 * 32768 + 2 * 32768;  // 230400
    static int smem_set = 0;
    if (!smem_set) {
        cudaFuncSetAttribute(mma_gemm<0>,
                             cudaFuncAttributeMaxDynamicSharedMemorySize, GEMM_SMEM);
        cudaFuncSetAttribute(mma_gemm<1>,
                             cudaFuncAttributeMaxDynamicSharedMemorySize, GEMM_SMEM);
        cudaFuncSetAttribute(attn_mma,
                             cudaFuncAttributeMaxDynamicSharedMemorySize, ATTN_SMEM);
        smem_set = 1;
    }

    // 1) qkv = x @ w_qkv^T (+scale_emb on K slice)
    {
        dim3 grid(3 * C_ / 128, (B_ * N_) / 128);   // (18, 64)
        mma_gemm<0><<<grid, 256, GEMM_SMEM>>>(x, wqkv, qkv, 3 * C_, C_, se);
    }
    // 2) tcgen05 attention (+ unnormalized probs, rowsums)
    {
        dim3 grid(N_ / 128, B_ * H_);               // (8, 96)
        attn_mma<<<grid, 256, ATTN_SMEM>>>(probs, rsum);
    }
    // 2b) normalize probs
    if (probs) {
        norm_kernel<<<B_ * H_ * N_, 256>>>(probs, rsum);
    }
    // 3) out = attn @ w_proj^T + b_proj
    if (do_proj) {
        dim3 grid(C_ / 128, (B_ * N_) / 128);       // (6, 64)
        mma_gemm<1><<<grid, 256, GEMM_SMEM>>>(attn, wproj, out, C_, C_, bproj);
    }
}